// round 1
// baseline (speedup 1.0000x reference)
#include <cuda_runtime.h>
#include <math.h>

// ---------------------------------------------------------------------------
// Problem constants (fixed instance)
// ---------------------------------------------------------------------------
constexpr int Bc  = 2;
constexpr int Cc  = 256;
constexpr int NHc = 8;
constexpr int Lc  = 4;
constexpr int Pc  = 4;
constexpr int Dc  = 32;          // C / NH
constexpr int LVc = 13294;       // 100*100 + 50*50 + 25*25 + 13*13
constexpr int LQc = 13294;
constexpr int Mrows = Bc * LQc;  // 26588
constexpr int PROJW = NHc * Lc * Pc * 2 + NHc * Lc * Pc; // 256 + 128 = 384

// Scratch (device globals; no allocation allowed)
__device__ float g_val [Bc * LVc * Cc];     // [b][lv][c]         ~27 MB
__device__ float g_proj[Bc * LQc * PROJW];  // [b][q][384]        ~41 MB
__device__ float g_msda[Bc * LQc * Cc];     // [b][q][c]          ~27 MB

// ---------------------------------------------------------------------------
// Tiled FP32 GEMM:  Cout = A(MxK=256) * W(256xN) + bias  (+ optional residual)
//   A_ILV:   A row m decomposes m = b*Lseq + s, element at A[(s*Bc+b)*256 + k]
//            (matches the (seq, B, C) input layout). Otherwise A[m*256 + k].
//   OUT_MODE 0: Cout[m*ldc + n]
//   OUT_MODE 1: Cout[(s*Bc+b)*256 + n] += resid (residual add, final output)
// Tiles: BM=128, BN=64, BK=16, 256 threads, 8x4 register blocking.
// ---------------------------------------------------------------------------
template<bool A_ILV, int OUT_MODE>
__global__ __launch_bounds__(256)
void sgemm(const float* __restrict__ A, const float* __restrict__ W,
           const float* __restrict__ bias, float* __restrict__ Cout,
           int M, int Lseq, int ldw, int ldc,
           const float* __restrict__ resid)
{
    __shared__ float As[16][132];   // [k][row], padded: bank-safe, 16B aligned
    __shared__ float Ws[16][68];    // [k][col]

    const int tid = threadIdx.x;
    const int tx = tid & 15;        // 0..15  -> 4 cols
    const int ty = tid >> 4;        // 0..15  -> 8 rows
    const int m0 = blockIdx.x * 128;
    const int n0 = blockIdx.y * 64;

    // Per-thread A-tile load slots (2 float4 each iteration)
    int arow[2], ac[2];
    const float* aptr[2];
    #pragma unroll
    for (int r = 0; r < 2; r++) {
        int idx = tid + r * 256;            // 0..511 float4 slots
        arow[r] = idx >> 2;                 // 0..127
        ac[r]   = (idx & 3) * 4;            // 0,4,8,12
        int m = m0 + arow[r];
        if (m < M) {
            int off;
            if (A_ILV) { int b = m / Lseq; int s = m - b * Lseq;
                         off = (s * Bc + b) * Cc; }
            else       { off = m * Cc; }
            aptr[r] = A + off;
        } else {
            aptr[r] = nullptr;
        }
    }

    float acc[8][4];
    #pragma unroll
    for (int i = 0; i < 8; i++)
        #pragma unroll
        for (int j = 0; j < 4; j++) acc[i][j] = 0.f;

    #pragma unroll 1
    for (int kk = 0; kk < Cc / 16; kk++) {
        const int kbase = kk * 16;

        #pragma unroll
        for (int r = 0; r < 2; r++) {
            float4 a4 = make_float4(0.f, 0.f, 0.f, 0.f);
            if (aptr[r]) a4 = *(const float4*)(aptr[r] + kbase + ac[r]);
            As[ac[r] + 0][arow[r]] = a4.x;
            As[ac[r] + 1][arow[r]] = a4.y;
            As[ac[r] + 2][arow[r]] = a4.z;
            As[ac[r] + 3][arow[r]] = a4.w;
        }
        {
            float4 w4 = *(const float4*)(W + (kbase + ty) * ldw + n0 + tx * 4);
            *(float4*)&Ws[ty][tx * 4] = w4;
        }
        __syncthreads();

        #pragma unroll
        for (int k = 0; k < 16; k++) {
            float4 a0 = *(const float4*)&As[k][ty * 8];
            float4 a1 = *(const float4*)&As[k][ty * 8 + 4];
            float4 b4 = *(const float4*)&Ws[k][tx * 4];
            float av[8] = {a0.x, a0.y, a0.z, a0.w, a1.x, a1.y, a1.z, a1.w};
            float bv[4] = {b4.x, b4.y, b4.z, b4.w};
            #pragma unroll
            for (int i = 0; i < 8; i++)
                #pragma unroll
                for (int j = 0; j < 4; j++)
                    acc[i][j] = fmaf(av[i], bv[j], acc[i][j]);
        }
        __syncthreads();
    }

    // Epilogue
    #pragma unroll
    for (int i = 0; i < 8; i++) {
        int m = m0 + ty * 8 + i;
        if (m >= M) continue;
        int obase;
        if (OUT_MODE == 1) {
            int b = m / Lseq; int s = m - b * Lseq;
            obase = (s * Bc + b) * Cc;
        } else {
            obase = m * ldc;
        }
        #pragma unroll
        for (int j = 0; j < 4; j++) {
            int n = n0 + tx * 4 + j;
            float v = acc[i][j] + bias[n];
            if (OUT_MODE == 1) v += resid[obase + n];
            Cout[obase + n] = v;
        }
    }
}

// ---------------------------------------------------------------------------
// Fused softmax + bilinear sampling.
// One block per (b,q). 8 warps = 8 heads; lane = d channel (D=32).
// ---------------------------------------------------------------------------
__global__ __launch_bounds__(256)
void msda_sample(const float* __restrict__ rp,
                 const float* __restrict__ val,
                 const float* __restrict__ proj,
                 float* __restrict__ msda)
{
    const int bq = blockIdx.x;              // b*LQ + q
    const int tid = threadIdx.x;
    const int h = tid >> 5;
    const int lane = tid & 31;
    const int b = bq / LQc;

    __shared__ float proj_s[PROJW];
    const float* prow = proj + (size_t)bq * PROJW;
    proj_s[tid] = prow[tid];
    if (tid < 128) proj_s[256 + tid] = prow[256 + tid];
    __syncthreads();

    // Softmax over the 16 (L*P) logits of this head (lanes 0..15 hold them)
    float lg = (lane < 16) ? proj_s[256 + h * 16 + lane] : -1e30f;
    float mx = lg;
    #pragma unroll
    for (int o = 8; o > 0; o >>= 1)
        mx = fmaxf(mx, __shfl_xor_sync(0xffffffffu, mx, o));
    float e = (lane < 16) ? expf(lg - mx) : 0.f;
    float sum = e;
    #pragma unroll
    for (int o = 8; o > 0; o >>= 1)
        sum += __shfl_xor_sync(0xffffffffu, sum, o);
    float attn_val = e / sum;   // valid for lanes 0..15

    const int HH[4] = {100, 50, 25, 13};
    const int ST[4] = {0, 10000, 12500, 13125};

    const float* vbase = val + (size_t)b * LVc * Cc + h * Dc + lane;
    const float* rpp = rp + (size_t)bq * Lc * 2;

    float acc = 0.f;
    #pragma unroll
    for (int l = 0; l < Lc; l++) {
        const int   Hl = HH[l];          // square levels: Wl == Hl
        const int   Wl = HH[l];
        const int   st = ST[l];
        const float fW = (float)Wl, fH = (float)Hl;
        float rpx = fminf(fmaxf(rpp[l * 2 + 0], 1e-5f), 1.f - 1e-5f);
        float rpy = fminf(fmaxf(rpp[l * 2 + 1], 1e-5f), 1.f - 1e-5f);

        #pragma unroll
        for (int p = 0; p < Pc; p++) {
            int j = ((h * Lc + l) * Pc + p) * 2;
            float locx = rpx + proj_s[j]     / fW;
            float locy = rpy + proj_s[j + 1] / fH;
            float x = locx * fW - 0.5f;
            float y = locy * fH - 0.5f;
            float x0f = floorf(x), y0f = floorf(y);
            int x0 = (int)x0f, y0 = (int)y0f;
            float wx = x - x0f, wy = y - y0f;

            float a = __shfl_sync(0xffffffffu, attn_val, l * 4 + p);

            float w00 = a * (1.f - wy) * (1.f - wx);
            float w01 = a * (1.f - wy) * wx;
            float w10 = a * wy * (1.f - wx);
            float w11 = a * wy * wx;

            int x1 = x0 + 1, y1 = y0 + 1;
            bool vx0 = (x0 >= 0) & (x0 < Wl);
            bool vx1 = (x1 >= 0) & (x1 < Wl);
            bool vy0 = (y0 >= 0) & (y0 < Hl);
            bool vy1 = (y1 >= 0) & (y1 < Hl);

            if (vy0 & vx0) acc = fmaf(w00, vbase[(size_t)(st + y0 * Wl + x0) * Cc], acc);
            if (vy0 & vx1) acc = fmaf(w01, vbase[(size_t)(st + y0 * Wl + x1) * Cc], acc);
            if (vy1 & vx0) acc = fmaf(w10, vbase[(size_t)(st + y1 * Wl + x0) * Cc], acc);
            if (vy1 & vx1) acc = fmaf(w11, vbase[(size_t)(st + y1 * Wl + x1) * Cc], acc);
        }
    }

    msda[(size_t)bq * Cc + h * Dc + lane] = acc;
}

// ---------------------------------------------------------------------------
extern "C" void kernel_launch(void* const* d_in, const int* in_sizes, int n_in,
                              void* d_out, int out_size)
{
    const float* query = (const float*)d_in[0];   // (LQ, B, C)
    const float* rp    = (const float*)d_in[1];   // (B, LQ, L, 2)
    const float* value = (const float*)d_in[2];   // (LV, B, C)
    // d_in[3] spatial_shapes, d_in[4] level_start_index : compile-time constants
    const float* Wv    = (const float*)d_in[5];
    const float* bv    = (const float*)d_in[6];
    const float* Woff  = (const float*)d_in[7];
    const float* boff  = (const float*)d_in[8];
    const float* Wattn = (const float*)d_in[9];
    const float* battn = (const float*)d_in[10];
    const float* Wo    = (const float*)d_in[11];
    const float* bo    = (const float*)d_in[12];
    float* out = (float*)d_out;

    float *valp, *projp, *msdap;
    cudaGetSymbolAddress((void**)&valp,  g_val);
    cudaGetSymbolAddress((void**)&projp, g_proj);
    cudaGetSymbolAddress((void**)&msdap, g_msda);

    const int gm = (Mrows + 127) / 128;   // 208

    // 1) value projection: g_val[b][lv][c] = value @ Wv + bv
    sgemm<true, 0><<<dim3(gm, 4), 256>>>(value, Wv, bv, valp,
                                         Mrows, LVc, 256, 256, nullptr);
    // 2) offset projection -> g_proj[:, 0:256]
    sgemm<true, 0><<<dim3(gm, 4), 256>>>(query, Woff, boff, projp,
                                         Mrows, LQc, 256, PROJW, nullptr);
    // 3) attention logits -> g_proj[:, 256:384]
    sgemm<true, 0><<<dim3(gm, 2), 256>>>(query, Wattn, battn, projp + 256,
                                         Mrows, LQc, 128, PROJW, nullptr);
    // 4) softmax + bilinear sampling -> g_msda
    msda_sample<<<Mrows, 256>>>(rp, valp, projp, msdap);
    // 5) output projection + bias + residual -> d_out (LQ, B, C)
    sgemm<false, 1><<<dim3(gm, 4), 256>>>(msdap, Wo, bo, out,
                                          Mrows, LQc, 256, 256, query);
}

// round 2
// speedup vs baseline: 1.3250x; 1.3250x over previous
#include <cuda_runtime.h>
#include <math.h>

// ---------------------------------------------------------------------------
// Problem constants (fixed instance)
// ---------------------------------------------------------------------------
constexpr int Bc  = 2;
constexpr int Cc  = 256;
constexpr int NHc = 8;
constexpr int Lc  = 4;
constexpr int Pc  = 4;
constexpr int Dc  = 32;          // C / NH
constexpr int LVc = 13294;       // 100*100 + 50*50 + 25*25 + 13*13
constexpr int LQc = 13294;
constexpr int Mrows = Bc * LQc;  // 26588
constexpr int PROJW = NHc * Lc * Pc * 2 + NHc * Lc * Pc; // 256 + 128 = 384

// Scratch (device globals; no allocation allowed)
__device__ float g_val [Bc * LVc * Cc];     // [b][lv][c]         ~27 MB
__device__ float g_proj[Bc * LQc * PROJW];  // [b][q][384]        ~41 MB
__device__ float g_msda[Bc * LQc * Cc];     // [b][q][c]          ~27 MB

// ---------------------------------------------------------------------------
// Tiled FP32 GEMM:  Cout = A(MxK=256) * W(256xN) + bias  (+ optional residual)
//   A_ILV:   A row m decomposes m = b*Lseq + s, element at A[(s*Bc+b)*256 + k]
//   OUT_MODE 0: Cout[m*ldc + n]
//   OUT_MODE 1: Cout[(s*Bc+b)*256 + n] += resid (residual add, final output)
// Tiles: BM=128, BN=128, BK=16, 256 threads, 8x8 register blocking.
// ---------------------------------------------------------------------------
template<bool A_ILV, int OUT_MODE>
__global__ __launch_bounds__(256)
void sgemm(const float* __restrict__ A, const float* __restrict__ W,
           const float* __restrict__ bias, float* __restrict__ Cout,
           int M, int Lseq, int ldw, int ldc,
           const float* __restrict__ resid)
{
    __shared__ float As[16][132];   // [k][row]
    __shared__ float Ws[16][132];   // [k][col]

    const int tid = threadIdx.x;
    const int tx = tid & 15;        // 0..15 -> 8 cols
    const int ty = tid >> 4;        // 0..15 -> 8 rows
    const int m0 = blockIdx.x * 128;
    const int n0 = blockIdx.y * 128;

    // A-tile load slots (2 float4 per k-tile)
    int arow[2], ac[2];
    const float* aptr[2];
    #pragma unroll
    for (int r = 0; r < 2; r++) {
        int idx = tid + r * 256;            // 0..511 float4 slots (128 rows x 4)
        arow[r] = idx >> 2;
        ac[r]   = (idx & 3) * 4;
        int m = m0 + arow[r];
        if (m < M) {
            int off;
            if (A_ILV) { int b = m / Lseq; int s = m - b * Lseq;
                         off = (s * Bc + b) * Cc; }
            else       { off = m * Cc; }
            aptr[r] = A + off;
        } else {
            aptr[r] = nullptr;
        }
    }
    // W-tile load slots (2 float4 per k-tile): 16 rows x 32 float4
    int wk[2], wc[2];
    #pragma unroll
    for (int r = 0; r < 2; r++) {
        int idx = tid + r * 256;
        wk[r] = idx >> 5;
        wc[r] = (idx & 31) * 4;
    }

    float acc[8][8];
    #pragma unroll
    for (int i = 0; i < 8; i++)
        #pragma unroll
        for (int j = 0; j < 8; j++) acc[i][j] = 0.f;

    #pragma unroll 1
    for (int kk = 0; kk < Cc / 16; kk++) {
        const int kbase = kk * 16;

        #pragma unroll
        for (int r = 0; r < 2; r++) {
            float4 a4 = make_float4(0.f, 0.f, 0.f, 0.f);
            if (aptr[r]) a4 = *(const float4*)(aptr[r] + kbase + ac[r]);
            As[ac[r] + 0][arow[r]] = a4.x;
            As[ac[r] + 1][arow[r]] = a4.y;
            As[ac[r] + 2][arow[r]] = a4.z;
            As[ac[r] + 3][arow[r]] = a4.w;
        }
        #pragma unroll
        for (int r = 0; r < 2; r++) {
            float4 w4 = *(const float4*)(W + (kbase + wk[r]) * ldw + n0 + wc[r]);
            *(float4*)&Ws[wk[r]][wc[r]] = w4;
        }
        __syncthreads();

        #pragma unroll
        for (int k = 0; k < 16; k++) {
            float4 a0 = *(const float4*)&As[k][ty * 8];
            float4 a1 = *(const float4*)&As[k][ty * 8 + 4];
            float4 b0 = *(const float4*)&Ws[k][tx * 8];
            float4 b1 = *(const float4*)&Ws[k][tx * 8 + 4];
            float av[8] = {a0.x, a0.y, a0.z, a0.w, a1.x, a1.y, a1.z, a1.w};
            float bv[8] = {b0.x, b0.y, b0.z, b0.w, b1.x, b1.y, b1.z, b1.w};
            #pragma unroll
            for (int i = 0; i < 8; i++)
                #pragma unroll
                for (int j = 0; j < 8; j++)
                    acc[i][j] = fmaf(av[i], bv[j], acc[i][j]);
        }
        __syncthreads();
    }

    // Bias for this thread's 8 columns
    float4 bb0 = *(const float4*)&bias[n0 + tx * 8];
    float4 bb1 = *(const float4*)&bias[n0 + tx * 8 + 4];
    float bvals[8] = {bb0.x, bb0.y, bb0.z, bb0.w, bb1.x, bb1.y, bb1.z, bb1.w};

    #pragma unroll
    for (int i = 0; i < 8; i++) {
        int m = m0 + ty * 8 + i;
        if (m >= M) continue;
        int obase;
        if (OUT_MODE == 1) {
            int b = m / Lseq; int s = m - b * Lseq;
            obase = (s * Bc + b) * Cc;
        } else {
            obase = m * ldc;
        }
        float v[8];
        #pragma unroll
        for (int j = 0; j < 8; j++) v[j] = acc[i][j] + bvals[j];
        if (OUT_MODE == 1) {
            const float4* rp0 = (const float4*)&resid[obase + n0 + tx * 8];
            float4 r0 = rp0[0], r1 = rp0[1];
            v[0] += r0.x; v[1] += r0.y; v[2] += r0.z; v[3] += r0.w;
            v[4] += r1.x; v[5] += r1.y; v[6] += r1.z; v[7] += r1.w;
        }
        float4* op = (float4*)&Cout[obase + n0 + tx * 8];
        op[0] = make_float4(v[0], v[1], v[2], v[3]);
        op[1] = make_float4(v[4], v[5], v[6], v[7]);
    }
}

// ---------------------------------------------------------------------------
// Fused softmax + bilinear sampling, vectorized.
// One block per (b,q). 8 warps = 8 heads.
// Lane decomposition: g = lane>>3 (point within level), cq = lane&7 (channel
// quad, float4 covers channels cq*4..cq*4+3). Round l = level (P==4 points).
// ---------------------------------------------------------------------------
__global__ __launch_bounds__(256)
void msda_sample(const float* __restrict__ rp,
                 const float* __restrict__ val,
                 const float* __restrict__ proj,
                 float* __restrict__ msda)
{
    const int bq   = blockIdx.x;            // b*LQ + q
    const int tid  = threadIdx.x;
    const int h    = tid >> 5;
    const int lane = tid & 31;
    const int g    = lane >> 3;             // point p = g
    const int cq   = lane & 7;              // channel quad
    const int b    = bq / LQc;

    __shared__ float proj_s[PROJW];
    __shared__ float rp_s[Lc * 2];
    const float* prow = proj + bq * PROJW;
    proj_s[tid] = prow[tid];
    if (tid < 128) proj_s[256 + tid] = prow[256 + tid];
    if (tid < Lc * 2) rp_s[tid] = rp[bq * Lc * 2 + tid];
    __syncthreads();

    // Softmax over the 16 (L*P) logits of this head (lanes 0..15 hold them)
    float lg = (lane < 16) ? proj_s[256 + h * 16 + lane] : -1e30f;
    float mx = lg;
    #pragma unroll
    for (int o = 8; o > 0; o >>= 1)
        mx = fmaxf(mx, __shfl_xor_sync(0xffffffffu, mx, o));
    float e = (lane < 16) ? __expf(lg - mx) : 0.f;
    float sum = e;
    #pragma unroll
    for (int o = 8; o > 0; o >>= 1)
        sum += __shfl_xor_sync(0xffffffffu, sum, o);
    float attn_val = e / sum;   // valid for lanes 0..15

    constexpr int   HH[4] = {100, 50, 25, 13};
    constexpr int   ST[4] = {0, 10000, 12500, 13125};

    // float4 base: val[b][.][h*32 + cq*4]
    const float4* vb = (const float4*)val + (b * LVc) * (Cc / 4) + h * 8 + cq;

    float4 acc = make_float4(0.f, 0.f, 0.f, 0.f);

    #pragma unroll
    for (int l = 0; l < Lc; l++) {
        const int   Wl = HH[l];
        const int   st = ST[l];
        const float fW = (float)HH[l];
        float rpx = fminf(fmaxf(rp_s[l * 2 + 0], 1e-5f), 1.f - 1e-5f);
        float rpy = fminf(fmaxf(rp_s[l * 2 + 1], 1e-5f), 1.f - 1e-5f);

        const int j = ((h * Lc + l) * Pc + g) * 2;
        float offx = proj_s[j];
        float offy = proj_s[j + 1];

        // x = (rp + off/W)*W - 0.5 = rp*W + off - 0.5   (square levels: H==W)
        float x = fmaf(rpx, fW, offx) - 0.5f;
        float y = fmaf(rpy, fW, offy) - 0.5f;
        float x0f = floorf(x), y0f = floorf(y);
        int x0 = (int)x0f, y0 = (int)y0f;
        float wx = x - x0f, wy = y - y0f;

        float a = __shfl_sync(0xffffffffu, attn_val, l * 4 + g);

        float w00 = a * (1.f - wy) * (1.f - wx);
        float w01 = a * (1.f - wy) * wx;
        float w10 = a * wy * (1.f - wx);
        float w11 = a * wy * wx;

        int x1 = x0 + 1, y1 = y0 + 1;
        bool vx0 = (x0 >= 0) & (x0 < Wl);
        bool vx1 = (x1 >= 0) & (x1 < Wl);
        bool vy0 = (y0 >= 0) & (y0 < Wl);
        bool vy1 = (y1 >= 0) & (y1 < Wl);

        int row0 = (st + y0 * Wl) * (Cc / 4);
        int row1 = row0 + Wl * (Cc / 4);

        if (vy0 & vx0) {
            float4 v = vb[row0 + x0 * (Cc / 4)];
            acc.x = fmaf(w00, v.x, acc.x); acc.y = fmaf(w00, v.y, acc.y);
            acc.z = fmaf(w00, v.z, acc.z); acc.w = fmaf(w00, v.w, acc.w);
        }
        if (vy0 & vx1) {
            float4 v = vb[row0 + x1 * (Cc / 4)];
            acc.x = fmaf(w01, v.x, acc.x); acc.y = fmaf(w01, v.y, acc.y);
            acc.z = fmaf(w01, v.z, acc.z); acc.w = fmaf(w01, v.w, acc.w);
        }
        if (vy1 & vx0) {
            float4 v = vb[row1 + x0 * (Cc / 4)];
            acc.x = fmaf(w10, v.x, acc.x); acc.y = fmaf(w10, v.y, acc.y);
            acc.z = fmaf(w10, v.z, acc.z); acc.w = fmaf(w10, v.w, acc.w);
        }
        if (vy1 & vx1) {
            float4 v = vb[row1 + x1 * (Cc / 4)];
            acc.x = fmaf(w11, v.x, acc.x); acc.y = fmaf(w11, v.y, acc.y);
            acc.z = fmaf(w11, v.z, acc.z); acc.w = fmaf(w11, v.w, acc.w);
        }
    }

    // Reduce across the 4 point-groups (lanes differing in bits 3,4)
    #pragma unroll
    for (int o = 8; o <= 16; o <<= 1) {
        acc.x += __shfl_xor_sync(0xffffffffu, acc.x, o);
        acc.y += __shfl_xor_sync(0xffffffffu, acc.y, o);
        acc.z += __shfl_xor_sync(0xffffffffu, acc.z, o);
        acc.w += __shfl_xor_sync(0xffffffffu, acc.w, o);
    }

    if (g == 0) {
        ((float4*)msda)[bq * (Cc / 4) + h * 8 + cq] = acc;
    }
}

// ---------------------------------------------------------------------------
extern "C" void kernel_launch(void* const* d_in, const int* in_sizes, int n_in,
                              void* d_out, int out_size)
{
    const float* query = (const float*)d_in[0];   // (LQ, B, C)
    const float* rp    = (const float*)d_in[1];   // (B, LQ, L, 2)
    const float* value = (const float*)d_in[2];   // (LV, B, C)
    const float* Wv    = (const float*)d_in[5];
    const float* bv    = (const float*)d_in[6];
    const float* Woff  = (const float*)d_in[7];
    const float* boff  = (const float*)d_in[8];
    const float* Wattn = (const float*)d_in[9];
    const float* battn = (const float*)d_in[10];
    const float* Wo    = (const float*)d_in[11];
    const float* bo    = (const float*)d_in[12];
    float* out = (float*)d_out;

    float *valp, *projp, *msdap;
    cudaGetSymbolAddress((void**)&valp,  g_val);
    cudaGetSymbolAddress((void**)&projp, g_proj);
    cudaGetSymbolAddress((void**)&msdap, g_msda);

    const int gm = (Mrows + 127) / 128;   // 208

    // 1) value projection: g_val[b][lv][c] = value @ Wv + bv
    sgemm<true, 0><<<dim3(gm, 2), 256>>>(value, Wv, bv, valp,
                                         Mrows, LVc, 256, 256, nullptr);
    // 2) offset projection -> g_proj[:, 0:256]
    sgemm<true, 0><<<dim3(gm, 2), 256>>>(query, Woff, boff, projp,
                                         Mrows, LQc, 256, PROJW, nullptr);
    // 3) attention logits -> g_proj[:, 256:384]
    sgemm<true, 0><<<dim3(gm, 1), 256>>>(query, Wattn, battn, projp + 256,
                                         Mrows, LQc, 128, PROJW, nullptr);
    // 4) softmax + bilinear sampling -> g_msda
    msda_sample<<<Mrows, 256>>>(rp, valp, projp, msdap);
    // 5) output projection + bias + residual -> d_out (LQ, B, C)
    sgemm<false, 1><<<dim3(gm, 2), 256>>>(msdap, Wo, bo, out,
                                          Mrows, LQc, 256, 256, query);
}